// round 2
// baseline (speedup 1.0000x reference)
#include <cuda_runtime.h>

typedef unsigned long long u64;
typedef unsigned int u32;

#define T_STEPS 2048
#define NB 8
#define NH 16
#define BH (NB*NH)
#define KF 32
#define VF 64
#define KS 128
#define VS 64

// packed f32x2 helpers (Blackwell packed fp32 pipe)
__device__ __forceinline__ u64 pack2(float lo, float hi) {
    u64 r;
    asm("mov.b64 %0, {%1, %2};" : "=l"(r) : "r"(__float_as_uint(lo)), "r"(__float_as_uint(hi)));
    return r;
}
__device__ __forceinline__ void unpack2(u64 a, float& lo, float& hi) {
    u32 l, h;
    asm("mov.b64 {%0, %1}, %2;" : "=r"(l), "=r"(h) : "l"(a));
    lo = __uint_as_float(l); hi = __uint_as_float(h);
}
__device__ __forceinline__ u64 fma2_(u64 a, u64 b, u64 c) {
    u64 d; asm("fma.rn.f32x2 %0, %1, %2, %3;" : "=l"(d) : "l"(a), "l"(b), "l"(c)); return d;
}
__device__ __forceinline__ u64 mul2_(u64 a, u64 b) {
    u64 d; asm("mul.rn.f32x2 %0, %1, %2;" : "=l"(d) : "l"(a), "l"(b)); return d;
}

// smem per-step buffer (floats):
// [0,32) kf | [32,64) qf | [64,192) ks (swizzled) | [192,320) qs (swizzled)
// [320,384) vf | [384,448) vs | [448,453) scalars {df, ds, g, mf, ms} | pad to 456
#define STEP_F 456

__global__ __launch_bounds__(256, 1)
void e90_kernel(const float* __restrict__ k_fast, const float* __restrict__ v_fast,
                const float* __restrict__ q_fast, const float* __restrict__ decay_fast,
                const float* __restrict__ k_slow, const float* __restrict__ v_slow,
                const float* __restrict__ q_slow, const float* __restrict__ decay_slow,
                const float* __restrict__ slow_gate, const float* __restrict__ mix_fast,
                const float* __restrict__ mix_slow, const float* __restrict__ S_fast0,
                const float* __restrict__ S_slow0, float* __restrict__ out)
{
    __shared__ __align__(16) float smem[2 * STEP_F];

    const int tid = threadIdx.x;
    const int bh  = blockIdx.x;
    const int kg  = tid & 3;    // k-group: which quarter of the K dimension
    const int vj  = tid >> 2;   // value column 0..63

    // ---- prefetch role: each thread stages at most one 16B chunk per step ----
    const float* src = 0;
    int   smoff  = -1;
    long  stride = 0;
    bool  wide   = true;
    {
        int c = tid;
        if (c < 8)        {              src = k_fast + (size_t)bh*KF + c*4;       smoff = c*4;                               stride = (long)BH*KF; }
        else if (c < 16)  { int g = c-8;  src = q_fast + (size_t)bh*KF + g*4;      smoff = 32  + g*4;                         stride = (long)BH*KF; }
        else if (c < 48)  { int g = c-16; src = k_slow + (size_t)bh*KS + g*4;      smoff = 64  + ((g&7)*4 + (g>>3))*4;        stride = (long)BH*KS; }
        else if (c < 80)  { int g = c-48; src = q_slow + (size_t)bh*KS + g*4;      smoff = 192 + ((g&7)*4 + (g>>3))*4;        stride = (long)BH*KS; }
        else if (c < 96)  { int g = c-80; src = v_fast + (size_t)bh*VF + g*4;      smoff = 320 + g*4;                         stride = (long)BH*VF; }
        else if (c < 112) { int g = c-96; src = v_slow + (size_t)bh*VS + g*4;      smoff = 384 + g*4;                         stride = (long)BH*VS; }
        else if (c < 117) {
            const float* arrs[5] = {decay_fast, decay_slow, slow_gate, mix_fast, mix_slow};
            src = arrs[c-112] + bh; smoff = 448 + (c-112); stride = (long)BH; wide = false;
        }
    }
    const bool pv = (smoff >= 0);

    // ---- prologue: stage step 0 ----
    if (pv) {
        if (wide) { float4 p = *(const float4*)src; *(float4*)(smem + smoff) = p; }
        else      { smem[smoff] = *src; }
        src += stride;
    }

    // ---- load initial states (rows packed in pairs: reg p holds rows (base+2p, base+2p+1), column vj) ----
    u64 Sf[4], Ss[16];
    {
        const float* p0 = S_fast0 + (size_t)bh*KF*VF + vj;
        #pragma unroll
        for (int p = 0; p < 4; p++) {
            int r = kg*8 + 2*p;
            Sf[p] = pack2(p0[(size_t)r*VF], p0[(size_t)(r+1)*VF]);
        }
        const float* p1 = S_slow0 + (size_t)bh*KS*VS + vj;
        #pragma unroll
        for (int p = 0; p < 16; p++) {
            int r = kg*32 + 2*p;
            Ss[p] = pack2(p1[(size_t)r*VS], p1[(size_t)(r+1)*VS]);
        }
    }
    __syncthreads();

    // output region: [S_f_final | S_s_final | output]
    float* outO = out + (size_t)BH*(KF*VF + KS*VS) + (size_t)bh*VF + vj;
    const bool writer = (kg == 0);

    for (int t = 0; t < T_STEPS; t++) {
        const float* cur = smem + (t & 1) * STEP_F;
        float*       nxt = smem + ((t + 1) & 1) * STEP_F;

        // issue next step's global load early (latency hidden by this step's compute)
        const bool pre = pv && (t + 1 < T_STEPS);
        float4 pf;
        if (pre) {
            if (wide) pf = *(const float4*)src;
            else      pf.x = *src;
        }

        // per-step scalars (smem broadcast)
        float4 sc4 = *(const float4*)(cur + 448);
        float df = sc4.x, ds = sc4.y, g = sc4.z, mf = sc4.w;
        float ms = cur[452];
        float de = 1.0f + g * (ds - 1.0f);          // effective slow decay: g*ds + (1-g)

        float vfv = cur[320 + vj];
        float vsv = g * cur[384 + vj];              // fold gate into the slow outer-product term
        u64 vf2 = pack2(vfv, vfv);
        u64 vs2 = pack2(vsv, vsv);
        u64 df2 = pack2(df, df);
        u64 de2 = pack2(de, de);
        u64 accf = 0ull, accs = 0ull;

        // ---- fast state: 4 row-pairs ----
        {
            const ulonglong2* kp = (const ulonglong2*)(cur + 0)  + kg*2;
            const ulonglong2* qp = (const ulonglong2*)(cur + 32) + kg*2;
            #pragma unroll
            for (int j = 0; j < 2; j++) {
                ulonglong2 kk = kp[j];
                ulonglong2 qq = qp[j];
                Sf[2*j]   = fma2_(df2, Sf[2*j],   mul2_(kk.x, vf2));
                accf      = fma2_(qq.x, Sf[2*j],   accf);
                Sf[2*j+1] = fma2_(df2, Sf[2*j+1], mul2_(kk.y, vf2));
                accf      = fma2_(qq.y, Sf[2*j+1], accf);
            }
        }
        // ---- slow state: 16 row-pairs (swizzled smem: slot q*4+kg -> conflict-free) ----
        {
            const ulonglong2* kp = (const ulonglong2*)(cur + 64)  + kg;
            const ulonglong2* qp = (const ulonglong2*)(cur + 192) + kg;
            #pragma unroll
            for (int q = 0; q < 8; q++) {
                ulonglong2 kk = kp[4*q];
                ulonglong2 qq = qp[4*q];
                Ss[2*q]   = fma2_(de2, Ss[2*q],   mul2_(kk.x, vs2));
                accs      = fma2_(qq.x, Ss[2*q],   accs);
                Ss[2*q+1] = fma2_(de2, Ss[2*q+1], mul2_(kk.y, vs2));
                accs      = fma2_(qq.y, Ss[2*q+1], accs);
            }
        }

        // mix + horizontal (row-pair) add + reduce across the 4 k-groups (lanes kg=0..3)
        float flo, fhi, slo, shi;
        unpack2(accf, flo, fhi);
        unpack2(accs, slo, shi);
        float o = mf * (flo + fhi) + ms * (slo + shi);
        o += __shfl_xor_sync(0xffffffffu, o, 1);
        o += __shfl_xor_sync(0xffffffffu, o, 2);
        if (writer) *outO = o;
        outO += (size_t)BH * VF;

        // commit next step's staged data, then barrier
        if (pre) {
            if (wide) *(float4*)(nxt + smoff) = pf;
            else      nxt[smoff] = pf.x;
            src += stride;
        }
        __syncthreads();
    }

    // ---- final states ----
    {
        float* oSf = out + (size_t)bh*KF*VF + vj;
        #pragma unroll
        for (int p = 0; p < 4; p++) {
            int r = kg*8 + 2*p;
            float lo, hi; unpack2(Sf[p], lo, hi);
            oSf[(size_t)r*VF]     = lo;
            oSf[(size_t)(r+1)*VF] = hi;
        }
        float* oSs = out + (size_t)BH*KF*VF + (size_t)bh*KS*VS + vj;
        #pragma unroll
        for (int p = 0; p < 16; p++) {
            int r = kg*32 + 2*p;
            float lo, hi; unpack2(Ss[p], lo, hi);
            oSs[(size_t)r*VS]     = lo;
            oSs[(size_t)(r+1)*VS] = hi;
        }
    }
}

extern "C" void kernel_launch(void* const* d_in, const int* in_sizes, int n_in,
                              void* d_out, int out_size) {
    (void)in_sizes; (void)n_in; (void)out_size;
    e90_kernel<<<BH, 256>>>(
        (const float*)d_in[0],  (const float*)d_in[1],  (const float*)d_in[2],
        (const float*)d_in[3],  (const float*)d_in[4],  (const float*)d_in[5],
        (const float*)d_in[6],  (const float*)d_in[7],  (const float*)d_in[8],
        (const float*)d_in[9],  (const float*)d_in[10], (const float*)d_in[11],
        (const float*)d_in[12], (float*)d_out);
}

// round 3
// speedup vs baseline: 2.3105x; 2.3105x over previous
#include <cuda_runtime.h>

typedef unsigned long long u64;
typedef unsigned int u32;

#define T_STEPS 2048
#define NB 8
#define NH 16
#define BH (NB*NH)
#define KF 32
#define VF 64
#define KS 128
#define VS 64

// packed f32x2 helpers (Blackwell packed fp32 pipe)
__device__ __forceinline__ u64 pack2(float lo, float hi) {
    u64 r;
    asm("mov.b64 %0, {%1, %2};" : "=l"(r) : "r"(__float_as_uint(lo)), "r"(__float_as_uint(hi)));
    return r;
}
__device__ __forceinline__ void unpack2(u64 a, float& lo, float& hi) {
    u32 l, h;
    asm("mov.b64 {%0, %1}, %2;" : "=r"(l), "=r"(h) : "l"(a));
    lo = __uint_as_float(l); hi = __uint_as_float(h);
}
__device__ __forceinline__ u64 fma2_(u64 a, u64 b, u64 c) {
    u64 d; asm("fma.rn.f32x2 %0, %1, %2, %3;" : "=l"(d) : "l"(a), "l"(b), "l"(c)); return d;
}
__device__ __forceinline__ u64 mul2_(u64 a, u64 b) {
    u64 d; asm("mul.rn.f32x2 %0, %1, %2;" : "=l"(d) : "l"(a), "l"(b)); return d;
}

// smem per-step stage (floats):
// [0,32) kf | [32,64) qf | [64,192) ks (swizzled) | [192,320) qs (swizzled)
// [320,384) vf | [384,448) vs | [448,453) scalars {df, ds, g, mf, ms} | pad to 456
#define STEP_F 456
#define NSTAGE 8          // ring stages (8 * 1824B = 14.6 KB)
#define PAIRS_AHEAD 3     // 3 committed pair-groups in flight = 6 steps of prefetch

__global__ __launch_bounds__(256, 1)
void e90_kernel(const float* __restrict__ k_fast, const float* __restrict__ v_fast,
                const float* __restrict__ q_fast, const float* __restrict__ decay_fast,
                const float* __restrict__ k_slow, const float* __restrict__ v_slow,
                const float* __restrict__ q_slow, const float* __restrict__ decay_slow,
                const float* __restrict__ slow_gate, const float* __restrict__ mix_fast,
                const float* __restrict__ mix_slow, const float* __restrict__ S_fast0,
                const float* __restrict__ S_slow0, float* __restrict__ out)
{
    __shared__ __align__(16) float smem[NSTAGE * STEP_F];

    const int tid = threadIdx.x;
    const int bh  = blockIdx.x;
    const int kg  = tid & 3;    // k-group: quarter of the K dimension
    const int vj  = tid >> 2;   // value column 0..63

    // ---- loader role: each loader thread copies one 16B (or 4B) chunk per step via cp.async ----
    const float* src = 0;
    int   smoff  = -1;
    long  stride = 0;
    bool  wide   = true;
    {
        int c = tid;
        if (c < 8)        {               src = k_fast + (size_t)bh*KF + c*4;      smoff = c*4;                               stride = (long)BH*KF; }
        else if (c < 16)  { int g = c-8;  src = q_fast + (size_t)bh*KF + g*4;      smoff = 32  + g*4;                         stride = (long)BH*KF; }
        else if (c < 48)  { int g = c-16; src = k_slow + (size_t)bh*KS + g*4;      smoff = 64  + ((g&7)*4 + (g>>3))*4;        stride = (long)BH*KS; }
        else if (c < 80)  { int g = c-48; src = q_slow + (size_t)bh*KS + g*4;      smoff = 192 + ((g&7)*4 + (g>>3))*4;        stride = (long)BH*KS; }
        else if (c < 96)  { int g = c-80; src = v_fast + (size_t)bh*VF + g*4;      smoff = 320 + g*4;                         stride = (long)BH*VF; }
        else if (c < 112) { int g = c-96; src = v_slow + (size_t)bh*VS + g*4;      smoff = 384 + g*4;                         stride = (long)BH*VS; }
        else if (c < 117) {
            const float* arrs[5] = {decay_fast, decay_slow, slow_gate, mix_fast, mix_slow};
            src = arrs[c-112] + bh; smoff = 448 + (c-112); stride = (long)BH; wide = false;
        }
    }
    const bool pv = (smoff >= 0);

    u32 smem_base;
    {
        u64 a = __cvta_generic_to_shared(smem);
        smem_base = (u32)a;
    }

    // issue cp.async for one step's chunk; advances src
    auto issue = [&](int step) {
        if (pv && step < T_STEPS) {
            u32 dst = smem_base + ((u32)((step & (NSTAGE-1)) * STEP_F + smoff)) * 4u;
            if (wide) {
                asm volatile("cp.async.cg.shared.global [%0], [%1], 16;" :: "r"(dst), "l"(src));
            } else {
                asm volatile("cp.async.ca.shared.global [%0], [%1], 4;" :: "r"(dst), "l"(src));
            }
            src += stride;
        }
    };

    // ---- prologue: issue 3 pair-groups (steps 0..5) ----
    #pragma unroll
    for (int p = 0; p < PAIRS_AHEAD; p++) {
        issue(2*p); issue(2*p + 1);
        asm volatile("cp.async.commit_group;");
    }

    // ---- load initial states (row pairs packed in f32x2; column vj) ----
    u64 Sf[4], Ss[16];
    {
        const float* p0 = S_fast0 + (size_t)bh*KF*VF + vj;
        #pragma unroll
        for (int p = 0; p < 4; p++) {
            int r = kg*8 + 2*p;
            Sf[p] = pack2(p0[(size_t)r*VF], p0[(size_t)(r+1)*VF]);
        }
        const float* p1 = S_slow0 + (size_t)bh*KS*VS + vj;
        #pragma unroll
        for (int p = 0; p < 16; p++) {
            int r = kg*32 + 2*p;
            Ss[p] = pack2(p1[(size_t)r*VS], p1[(size_t)(r+1)*VS]);
        }
    }

    // output region: [S_f_final | S_s_final | output]
    float* outO = out + (size_t)BH*(KF*VF + KS*VS) + (size_t)bh*VF + vj;
    const bool writer = (kg == 0);

    for (int t = 0; t < T_STEPS; t += 2) {
        // steps t and t+1 must be resident: wait until only 2 newer pair-groups remain
        asm volatile("cp.async.wait_group 2;");
        __syncthreads();

        // refill: issue steps t+6, t+7 (one pair-group)
        issue(t + 2*PAIRS_AHEAD); issue(t + 2*PAIRS_AHEAD + 1);
        asm volatile("cp.async.commit_group;");

        #pragma unroll
        for (int s = 0; s < 2; s++) {
            const int   ts  = t + s;
            const float* cur = smem + (ts & (NSTAGE-1)) * STEP_F;

            float4 sc4 = *(const float4*)(cur + 448);
            float df = sc4.x, ds = sc4.y, g = sc4.z, mf = sc4.w;
            float ms = cur[452];
            float de = 1.0f + g * (ds - 1.0f);      // g*ds + (1-g)

            float vfv = cur[320 + vj];
            float vsv = g * cur[384 + vj];          // fold gate into slow outer product
            u64 vf2 = pack2(vfv, vfv);
            u64 vs2 = pack2(vsv, vsv);
            u64 df2 = pack2(df, df);
            u64 de2 = pack2(de, de);
            u64 accf0 = 0ull, accf1 = 0ull, accs0 = 0ull, accs1 = 0ull;

            // fast state: 4 row-pairs
            {
                const ulonglong2* kp = (const ulonglong2*)(cur + 0)  + kg*2;
                const ulonglong2* qp = (const ulonglong2*)(cur + 32) + kg*2;
                #pragma unroll
                for (int j = 0; j < 2; j++) {
                    ulonglong2 kk = kp[j];
                    ulonglong2 qq = qp[j];
                    Sf[2*j]   = fma2_(df2, Sf[2*j],   mul2_(kk.x, vf2));
                    accf0     = fma2_(qq.x, Sf[2*j],   accf0);
                    Sf[2*j+1] = fma2_(df2, Sf[2*j+1], mul2_(kk.y, vf2));
                    accf1     = fma2_(qq.y, Sf[2*j+1], accf1);
                }
            }
            // slow state: 16 row-pairs (swizzled smem -> conflict-free LDS.128)
            {
                const ulonglong2* kp = (const ulonglong2*)(cur + 64)  + kg;
                const ulonglong2* qp = (const ulonglong2*)(cur + 192) + kg;
                #pragma unroll
                for (int q = 0; q < 8; q++) {
                    ulonglong2 kk = kp[4*q];
                    ulonglong2 qq = qp[4*q];
                    Ss[2*q]   = fma2_(de2, Ss[2*q],   mul2_(kk.x, vs2));
                    accs0     = fma2_(qq.x, Ss[2*q],   accs0);
                    Ss[2*q+1] = fma2_(de2, Ss[2*q+1], mul2_(kk.y, vs2));
                    accs1     = fma2_(qq.y, Ss[2*q+1], accs1);
                }
            }

            u64 accf = fma2_(pack2(1.0f,1.0f), accf0, accf1); // accf0+accf1
            u64 accs = fma2_(pack2(1.0f,1.0f), accs0, accs1);
            float flo, fhi, slo, shi;
            unpack2(accf, flo, fhi);
            unpack2(accs, slo, shi);
            float o = mf * (flo + fhi) + ms * (slo + shi);
            o += __shfl_xor_sync(0xffffffffu, o, 1);
            o += __shfl_xor_sync(0xffffffffu, o, 2);
            if (writer) *outO = o;
            outO += (size_t)BH * VF;
        }
    }

    // ---- final states ----
    {
        float* oSf = out + (size_t)bh*KF*VF + vj;
        #pragma unroll
        for (int p = 0; p < 4; p++) {
            int r = kg*8 + 2*p;
            float lo, hi; unpack2(Sf[p], lo, hi);
            oSf[(size_t)r*VF]     = lo;
            oSf[(size_t)(r+1)*VF] = hi;
        }
        float* oSs = out + (size_t)BH*KF*VF + (size_t)bh*KS*VS + vj;
        #pragma unroll
        for (int p = 0; p < 16; p++) {
            int r = kg*32 + 2*p;
            float lo, hi; unpack2(Ss[p], lo, hi);
            oSs[(size_t)r*VS]     = lo;
            oSs[(size_t)(r+1)*VS] = hi;
        }
    }
}

extern "C" void kernel_launch(void* const* d_in, const int* in_sizes, int n_in,
                              void* d_out, int out_size) {
    (void)in_sizes; (void)n_in; (void)out_size;
    e90_kernel<<<BH, 256>>>(
        (const float*)d_in[0],  (const float*)d_in[1],  (const float*)d_in[2],
        (const float*)d_in[3],  (const float*)d_in[4],  (const float*)d_in[5],
        (const float*)d_in[6],  (const float*)d_in[7],  (const float*)d_in[8],
        (const float*)d_in[9],  (const float*)d_in[10], (const float*)d_in[11],
        (const float*)d_in[12], (float*)d_out);
}

// round 4
// speedup vs baseline: 3.4186x; 1.4796x over previous
#include <cuda_runtime.h>

typedef unsigned long long u64;
typedef unsigned int u32;

#define T_STEPS 2048
#define NB 8
#define NH 16
#define BH (NB*NH)
#define KF 32
#define VF 64
#define KS 128
#define VS 64

// ---- packed f32x2 helpers (Blackwell packed fp32 pipe) ----
__device__ __forceinline__ u64 pack2(float lo, float hi) {
    u64 r;
    asm("mov.b64 %0, {%1, %2};" : "=l"(r) : "r"(__float_as_uint(lo)), "r"(__float_as_uint(hi)));
    return r;
}
__device__ __forceinline__ void unpack2(u64 a, float& lo, float& hi) {
    u32 l, h;
    asm("mov.b64 {%0, %1}, %2;" : "=r"(l), "=r"(h) : "l"(a));
    lo = __uint_as_float(l); hi = __uint_as_float(h);
}
__device__ __forceinline__ u64 fma2_(u64 a, u64 b, u64 c) {
    u64 d; asm("fma.rn.f32x2 %0, %1, %2, %3;" : "=l"(d) : "l"(a), "l"(b), "l"(c)); return d;
}
__device__ __forceinline__ u64 mul2_(u64 a, u64 b) {
    u64 d; asm("mul.rn.f32x2 %0, %1, %2;" : "=l"(d) : "l"(a), "l"(b)); return d;
}
__device__ __forceinline__ u64 add2_(u64 a, u64 b) {
    u64 d; asm("add.rn.f32x2 %0, %1, %2;" : "=l"(d) : "l"(a), "l"(b)); return d;
}
__device__ __forceinline__ u64 shfl_xor16_u64(u64 v, int m) {
    u32 lo, hi;
    asm("mov.b64 {%0, %1}, %2;" : "=r"(lo), "=r"(hi) : "l"(v));
    lo = __shfl_xor_sync(0xffffffffu, lo, m, 16);
    hi = __shfl_xor_sync(0xffffffffu, hi, m, 16);
    u64 r;
    asm("mov.b64 %0, {%1, %2};" : "=l"(r) : "r"(lo), "r"(hi));
    return r;
}

// smem per-step stage (floats):
// [0,32)    kf (natural order, rows)
// [32,64)   qf
// [64,192)  ks : 32 chunks of 4 rows; chunk g at 64 + (g>>1)*4 + (g&1)*64
//                (even chunks [64,128), odd chunks [128,192)) -> 16B lane stride
// [192,320) qs : same split layout
// [320,384) vf | [384,448) vs | [448,453) scalars {df, ds, g, mf, ms} | pad to 456
#define STEP_F 456
#define NSTAGE 8
#define PAIRS_AHEAD 3     // 3 committed pair-groups in flight = 6 steps of prefetch

__global__ __launch_bounds__(256, 1)
void e90_kernel(const float* __restrict__ k_fast, const float* __restrict__ v_fast,
                const float* __restrict__ q_fast, const float* __restrict__ decay_fast,
                const float* __restrict__ k_slow, const float* __restrict__ v_slow,
                const float* __restrict__ q_slow, const float* __restrict__ decay_slow,
                const float* __restrict__ slow_gate, const float* __restrict__ mix_fast,
                const float* __restrict__ mix_slow, const float* __restrict__ S_fast0,
                const float* __restrict__ S_slow0, float* __restrict__ out)
{
    __shared__ __align__(16) float smem[NSTAGE * STEP_F];

    const int tid = threadIdx.x;
    const int bh  = blockIdx.x;
    const int kgp = tid & 15;   // k-group (16 groups)
    const int cg  = tid >> 4;   // column-group (16 groups of 4 columns)

    // ---- loader role: each loader thread copies one 16B (or 4B) chunk per step via cp.async ----
    const float* src = 0;
    int   smoff  = -1;
    long  stride = 0;
    bool  wide   = true;
    {
        int c = tid;
        if (c < 8)        {               src = k_fast + (size_t)bh*KF + c*4;      smoff = c*4;                                stride = (long)BH*KF; }
        else if (c < 16)  { int g = c-8;  src = q_fast + (size_t)bh*KF + g*4;      smoff = 32  + g*4;                          stride = (long)BH*KF; }
        else if (c < 48)  { int g = c-16; src = k_slow + (size_t)bh*KS + g*4;      smoff = 64  + (g>>1)*4 + (g&1)*64;          stride = (long)BH*KS; }
        else if (c < 80)  { int g = c-48; src = q_slow + (size_t)bh*KS + g*4;      smoff = 192 + (g>>1)*4 + (g&1)*64;          stride = (long)BH*KS; }
        else if (c < 96)  { int g = c-80; src = v_fast + (size_t)bh*VF + g*4;      smoff = 320 + g*4;                          stride = (long)BH*VF; }
        else if (c < 112) { int g = c-96; src = v_slow + (size_t)bh*VS + g*4;      smoff = 384 + g*4;                          stride = (long)BH*VS; }
        else if (c < 117) {
            const float* arrs[5] = {decay_fast, decay_slow, slow_gate, mix_fast, mix_slow};
            src = arrs[c-112] + bh; smoff = 448 + (c-112); stride = (long)BH; wide = false;
        }
    }
    const bool pv = (smoff >= 0);

    u32 smem_base;
    {
        u64 a = __cvta_generic_to_shared(smem);
        smem_base = (u32)a;
    }

    auto issue = [&](int step) {
        if (pv && step < T_STEPS) {
            u32 dst = smem_base + ((u32)((step & (NSTAGE-1)) * STEP_F + smoff)) * 4u;
            if (wide) {
                asm volatile("cp.async.cg.shared.global [%0], [%1], 16;" :: "r"(dst), "l"(src));
            } else {
                asm volatile("cp.async.ca.shared.global [%0], [%1], 4;" :: "r"(dst), "l"(src));
            }
            src += stride;
        }
    };

    // ---- prologue: issue 3 pair-groups (steps 0..5) ----
    #pragma unroll
    for (int p = 0; p < PAIRS_AHEAD; p++) {
        issue(2*p); issue(2*p + 1);
        asm volatile("cp.async.commit_group;");
    }

    // ---- load initial states ----
    // Fast: rows 2*kgp, 2*kgp+1 ; cols cg*4..cg*4+3. Sf[j] = (row_even, row_odd) col j.
    // Slow: rows 8*kgp+2p, +2p+1 (p=0..3) ; cols cg*4..+3. Ss[p][j].
    u64 Sf[4], Ss[4][4];
    {
        const float* p0 = S_fast0 + (size_t)bh*KF*VF + (size_t)(2*kgp)*VF + cg*4;
        float4 re = *(const float4*)p0;
        float4 ro = *(const float4*)(p0 + VF);
        Sf[0] = pack2(re.x, ro.x); Sf[1] = pack2(re.y, ro.y);
        Sf[2] = pack2(re.z, ro.z); Sf[3] = pack2(re.w, ro.w);

        #pragma unroll
        for (int p = 0; p < 4; p++) {
            const float* p1 = S_slow0 + (size_t)bh*KS*VS + (size_t)(8*kgp + 2*p)*VS + cg*4;
            float4 se = *(const float4*)p1;
            float4 so = *(const float4*)(p1 + VS);
            Ss[p][0] = pack2(se.x, so.x); Ss[p][1] = pack2(se.y, so.y);
            Ss[p][2] = pack2(se.z, so.z); Ss[p][3] = pack2(se.w, so.w);
        }
    }

    // output region: [S_f_final | S_s_final | output]
    float* outO = out + (size_t)BH*(KF*VF + KS*VS) + (size_t)bh*VF + cg*4;
    const bool writer = (kgp == 0);

    for (int t = 0; t < T_STEPS; t += 2) {
        asm volatile("cp.async.wait_group 2;");
        __syncthreads();

        // refill: issue steps t+6, t+7
        issue(t + 2*PAIRS_AHEAD); issue(t + 2*PAIRS_AHEAD + 1);
        asm volatile("cp.async.commit_group;");

        #pragma unroll
        for (int s = 0; s < 2; s++) {
            const float* cur = smem + ((t + s) & (NSTAGE-1)) * STEP_F;

            float4 sc4 = *(const float4*)(cur + 448);
            float df = sc4.x, ds = sc4.y, g = sc4.z, mf = sc4.w;
            float ms = cur[452];
            float de = 1.0f + g * (ds - 1.0f);          // g*ds + (1-g)

            u64 df2 = pack2(df, df);
            u64 de2 = pack2(de, de);

            float4 vf4 = *(const float4*)(cur + 320 + cg*4);
            float4 vs4 = *(const float4*)(cur + 384 + cg*4);
            u64 vf2[4] = { pack2(vf4.x, vf4.x), pack2(vf4.y, vf4.y),
                           pack2(vf4.z, vf4.z), pack2(vf4.w, vf4.w) };
            float w0 = g*vs4.x, w1 = g*vs4.y, w2 = g*vs4.z, w3 = g*vs4.w;
            u64 vs2[4] = { pack2(w0, w0), pack2(w1, w1), pack2(w2, w2), pack2(w3, w3) };

            // ---- fast state (1 row-pair x 4 cols) ----
            u64 kf = *(const u64*)(cur + 2*kgp);
            u64 qf = *(const u64*)(cur + 32 + 2*kgp);
            u64 accf[4];
            #pragma unroll
            for (int j = 0; j < 4; j++) {
                Sf[j]   = fma2_(df2, Sf[j], mul2_(kf, vf2[j]));
                accf[j] = mul2_(qf, Sf[j]);
            }

            // ---- slow state (4 row-pairs x 4 cols) ----
            ulonglong2 kA = *(const ulonglong2*)(cur + 64  + kgp*4);   // pairs 0,1
            ulonglong2 kB = *(const ulonglong2*)(cur + 128 + kgp*4);   // pairs 2,3
            ulonglong2 qA = *(const ulonglong2*)(cur + 192 + kgp*4);
            ulonglong2 qB = *(const ulonglong2*)(cur + 256 + kgp*4);
            u64 kk[4] = { kA.x, kA.y, kB.x, kB.y };
            u64 qq[4] = { qA.x, qA.y, qB.x, qB.y };
            u64 accs[4];
            #pragma unroll
            for (int j = 0; j < 4; j++) {
                Ss[0][j] = fma2_(de2, Ss[0][j], mul2_(kk[0], vs2[j]));
                accs[j]  = mul2_(qq[0], Ss[0][j]);
            }
            #pragma unroll
            for (int p = 1; p < 4; p++) {
                #pragma unroll
                for (int j = 0; j < 4; j++) {
                    Ss[p][j] = fma2_(de2, Ss[p][j], mul2_(kk[p], vs2[j]));
                    accs[j]  = fma2_(qq[p], Ss[p][j], accs[j]);
                }
            }

            // ---- mix + horizontal (row-pair) sum ----
            u64 mf2 = pack2(mf, mf), ms2 = pack2(ms, ms);
            float o[4];
            #pragma unroll
            for (int j = 0; j < 4; j++) {
                u64 m = fma2_(ms2, accs[j], mul2_(mf2, accf[j]));
                float lo, hi; unpack2(m, lo, hi);
                o[j] = lo + hi;
            }
            u64 o01 = pack2(o[0], o[1]);
            u64 o23 = pack2(o[2], o[3]);

            // ---- reduce across the 16 k-groups (lanes, width 16) ----
            #pragma unroll
            for (int m = 1; m < 16; m <<= 1) {
                o01 = add2_(o01, shfl_xor16_u64(o01, m));
                o23 = add2_(o23, shfl_xor16_u64(o23, m));
            }
            if (writer) {
                float a0, a1, a2, a3;
                unpack2(o01, a0, a1);
                unpack2(o23, a2, a3);
                *(float4*)outO = make_float4(a0, a1, a2, a3);
            }
            outO += (size_t)BH * VF;
        }
    }

    // ---- final states ----
    {
        float* oSf = out + (size_t)bh*KF*VF + (size_t)(2*kgp)*VF + cg*4;
        float e0,o0,e1,o1,e2,o2,e3,o3;
        unpack2(Sf[0], e0, o0); unpack2(Sf[1], e1, o1);
        unpack2(Sf[2], e2, o2); unpack2(Sf[3], e3, o3);
        *(float4*)oSf        = make_float4(e0, e1, e2, e3);
        *(float4*)(oSf + VF) = make_float4(o0, o1, o2, o3);

        #pragma unroll
        for (int p = 0; p < 4; p++) {
            float* oSs = out + (size_t)BH*KF*VF + (size_t)bh*KS*VS + (size_t)(8*kgp + 2*p)*VS + cg*4;
            float se0,so0,se1,so1,se2,so2,se3,so3;
            unpack2(Ss[p][0], se0, so0); unpack2(Ss[p][1], se1, so1);
            unpack2(Ss[p][2], se2, so2); unpack2(Ss[p][3], se3, so3);
            *(float4*)oSs        = make_float4(se0, se1, se2, se3);
            *(float4*)(oSs + VS) = make_float4(so0, so1, so2, so3);
        }
    }
}

extern "C" void kernel_launch(void* const* d_in, const int* in_sizes, int n_in,
                              void* d_out, int out_size) {
    (void)in_sizes; (void)n_in; (void)out_size;
    e90_kernel<<<BH, 256>>>(
        (const float*)d_in[0],  (const float*)d_in[1],  (const float*)d_in[2],
        (const float*)d_in[3],  (const float*)d_in[4],  (const float*)d_in[5],
        (const float*)d_in[6],  (const float*)d_in[7],  (const float*)d_in[8],
        (const float*)d_in[9],  (const float*)d_in[10], (const float*)d_in[11],
        (const float*)d_in[12], (float*)d_out);
}